// round 6
// baseline (speedup 1.0000x reference)
#include <cuda_runtime.h>

#define N_NODES 50000
#define E_EDGES 800000
#define D 128
#define D4 32   // D in float4 units
#define NPB 32  // nodes per fused block (2 m-groups of 16)

// Scratch (allocation-free rule: __device__ globals)
__device__ float4 g_h1[N_NODES * D4];
__device__ float4 g_h2[N_NODES * D4];
__device__ int    g_deg[N_NODES];
__device__ int    g_rowptr[N_NODES + 1];
__device__ int    g_cursor[N_NODES];
__device__ int    g_csrc[E_EDGES];

// ---------------------------------------------------------------------------
// packed f32x2 helpers
// ---------------------------------------------------------------------------
__device__ __forceinline__ void fma2(unsigned long long& d,
                                     unsigned long long a,
                                     unsigned long long b) {
    asm("fma.rn.f32x2 %0, %1, %2, %0;" : "+l"(d) : "l"(a), "l"(b));
}
__device__ __forceinline__ unsigned long long pack2(float lo, float hi) {
    unsigned long long r;
    asm("mov.b64 %0, {%1, %2};" : "=l"(r) : "f"(lo), "f"(hi));
    return r;
}
__device__ __forceinline__ float sum2(unsigned long long v) {
    float lo, hi;
    asm("mov.b64 {%0, %1}, %2;" : "=f"(lo), "=f"(hi) : "l"(v));
    return lo + hi;
}

// ---------------------------------------------------------------------------
// CSR build: zero degrees -> histogram -> scan -> fill src lists
// ---------------------------------------------------------------------------
__global__ void zero_deg_kernel() {
    int i = blockIdx.x * blockDim.x + threadIdx.x;
    if (i < N_NODES) g_deg[i] = 0;
}

__global__ void hist_kernel(const int* __restrict__ dst, int E) {
    int e = blockIdx.x * blockDim.x + threadIdx.x;
    if (e < E) atomicAdd(&g_deg[__ldg(dst + e)], 1);
}

__device__ __forceinline__ int warp_incl_scan(int v, int lane) {
    #pragma unroll
    for (int o = 1; o < 32; o <<= 1) {
        int t = __shfl_up_sync(0xFFFFFFFFu, v, o);
        if (lane >= o) v += t;
    }
    return v;
}

__global__ void __launch_bounds__(1024) scan_kernel() {
    __shared__ int s_warp[32];
    __shared__ int s_carry;
    int tid = threadIdx.x;
    int lane = tid & 31, wid = tid >> 5;
    if (tid == 0) s_carry = 0;
    __syncthreads();

    for (int base = 0; base < N_NODES; base += 1024) {
        int idx = base + tid;
        int v = (idx < N_NODES) ? g_deg[idx] : 0;
        int incl = warp_incl_scan(v, lane);
        if (lane == 31) s_warp[wid] = incl;
        __syncthreads();
        if (wid == 0) {
            int w = s_warp[lane];
            w = warp_incl_scan(w, lane);
            s_warp[lane] = w;
        }
        __syncthreads();
        int offset = (wid > 0) ? s_warp[wid - 1] : 0;
        int excl = s_carry + offset + incl - v;
        if (idx < N_NODES) {
            g_rowptr[idx] = excl;
            g_cursor[idx] = excl;
        }
        int chunk_total = s_warp[31];
        __syncthreads();
        if (tid == 0) s_carry += chunk_total;
        __syncthreads();
    }
    if (tid == 0) g_rowptr[N_NODES] = s_carry;
}

__global__ void fill_kernel(const int* __restrict__ src,
                            const int* __restrict__ dst, int E) {
    int e = blockIdx.x * blockDim.x + threadIdx.x;
    if (e >= E) return;
    int d = __ldg(dst + e);
    int pos = atomicAdd(&g_cursor[d], 1);
    g_csrc[pos] = __ldg(src + e);
}

// ---------------------------------------------------------------------------
// FUSED kernel: per block of NPB=32 nodes:
//   phase 1: stage hin rows + gather-aggregate neighborhoods into smem
//   phase 2: dual GEMM (Wl x agg + Wr x hin + bl) with f32x2 packed FMA,
//            weights staged via smem (coalesced LDG, conflict-free LDS)
//   epilogue: MODE 0 LayerNorm->ReLU ; MODE 1 ReLU ; MODE 2 identity
// ---------------------------------------------------------------------------
#define WROW 9  // float4 per wbuf row (2*4 data + 1 pad -> odd in 16B units)

template <int MODE>
__global__ void __launch_bounds__(128)
fused_kernel(const float4* __restrict__ hin,
             const float* __restrict__ Wl,
             const float* __restrict__ bl,
             const float* __restrict__ Wr,
             const float* __restrict__ lng,
             const float* __restrict__ lnb,
             float* __restrict__ out) {
    // [node][64] float4 : agg row (32) | hin row (32)
    __shared__ float4 s_in[NPB * 64];          // 32 KB
    __shared__ float4 wbuf[64 * WROW];         // 9 KB weight staging
    __shared__ float s_mu[NPB], s_rs[NPB];

    const int tid = threadIdx.x;
    const int n0 = blockIdx.x * NPB;
    const int lane = tid & 31;
    const int warp = tid >> 5;

    // ---- phase 1a: stage hin rows (coalesced; 128 threads = 4 node rows/pass)
    #pragma unroll
    for (int i = tid; i < NPB * 32; i += 128) {
        int m = i >> 5, q = i & 31;
        int n = n0 + m;
        if (n >= N_NODES) n = N_NODES - 1;  // clamp
        s_in[m * 64 + 32 + q] = __ldg(hin + n * D4 + q);
    }

    // ---- phase 1b: gather-aggregate. warp handles nodes [warp*8, warp*8+8)
    {
        int mfirst = warp * 8;
        // prefetch row pointers for all 8 nodes (9 values)
        int rp[9];
        #pragma unroll
        for (int u = 0; u < 9; u++) {
            int n = n0 + mfirst + u;
            rp[u] = (n <= N_NODES) ? __ldg(g_rowptr + n) : 0;
        }
        #pragma unroll 1
        for (int u = 0; u < 8; u++) {
            int n = n0 + mfirst + u;
            float4 a = make_float4(0.f, 0.f, 0.f, 0.f);
            if (n < N_NODES) {
                int beg = rp[u], end = rp[u + 1];
                int i = beg;
                for (; i + 8 <= end; i += 8) {
                    int s[8];
                    #pragma unroll
                    for (int q = 0; q < 8; q++) s[q] = __ldg(g_csrc + i + q);
                    float4 v[8];
                    #pragma unroll
                    for (int q = 0; q < 8; q++) v[q] = __ldg(hin + s[q] * D4 + lane);
                    float4 t0, t1, t2, t3;
                    t0.x = v[0].x + v[1].x; t0.y = v[0].y + v[1].y; t0.z = v[0].z + v[1].z; t0.w = v[0].w + v[1].w;
                    t1.x = v[2].x + v[3].x; t1.y = v[2].y + v[3].y; t1.z = v[2].z + v[3].z; t1.w = v[2].w + v[3].w;
                    t2.x = v[4].x + v[5].x; t2.y = v[4].y + v[5].y; t2.z = v[4].z + v[5].z; t2.w = v[4].w + v[5].w;
                    t3.x = v[6].x + v[7].x; t3.y = v[6].y + v[7].y; t3.z = v[6].z + v[7].z; t3.w = v[6].w + v[7].w;
                    t0.x += t1.x; t0.y += t1.y; t0.z += t1.z; t0.w += t1.w;
                    t2.x += t3.x; t2.y += t3.y; t2.z += t3.z; t2.w += t3.w;
                    a.x += t0.x + t2.x; a.y += t0.y + t2.y; a.z += t0.z + t2.z; a.w += t0.w + t2.w;
                }
                for (; i < end; i++) {
                    int s = __ldg(g_csrc + i);
                    float4 v = __ldg(hin + s * D4 + lane);
                    a.x += v.x; a.y += v.y; a.z += v.z; a.w += v.w;
                }
            }
            s_in[(mfirst + u) * 64 + lane] = a;
        }
    }

    const ulonglong2* s_u = reinterpret_cast<const ulonglong2*>(s_in);
    const int jh = tid & 63;           // j pair index
    const int j0 = 2 * jh;
    const int mg = tid >> 6;           // m-group: 0 or 1
    const int mbase = mg * 16;

    unsigned long long acc2[16][2];
    {
        unsigned long long ba = pack2(__ldg(bl + j0), 0.0f);
        unsigned long long bb = pack2(__ldg(bl + j0 + 1), 0.0f);
        #pragma unroll
        for (int m = 0; m < 16; m++) { acc2[m][0] = ba; acc2[m][1] = bb; }
    }

    // ---- phase 2: dual GEMM. h=0 -> Wl vs agg (cols 0..31), h=1 -> Wr vs hin
    #pragma unroll 1
    for (int h = 0; h < 2; h++) {
        const float4* Wg = reinterpret_cast<const float4*>(h ? Wr : Wl);
        #pragma unroll 1
        for (int kc = 0; kc < 8; kc++) {       // 8 chunks of 4 k4 (16 k)
            __syncthreads();
            {   // stage: thread = weight row j, 4 contiguous float4
                int j = tid;
                const float4* srcp = Wg + j * 32 + kc * 4;
                float4* dstp = &wbuf[(j >> 1) * WROW + (j & 1)];
                #pragma unroll
                for (int q = 0; q < 4; q++) dstp[2 * q] = __ldg(srcp + q);
            }
            __syncthreads();
            #pragma unroll
            for (int k4 = 0; k4 < 4; k4++) {
                ulonglong2 wa = *reinterpret_cast<const ulonglong2*>(&wbuf[jh * WROW + 2 * k4]);
                ulonglong2 wb = *reinterpret_cast<const ulonglong2*>(&wbuf[jh * WROW + 2 * k4 + 1]);
                int kk = h * 32 + kc * 4 + k4;
                #pragma unroll
                for (int m = 0; m < 16; m++) {
                    ulonglong2 v = s_u[(mbase + m) * 64 + kk];
                    fma2(acc2[m][0], wa.x, v.x);
                    fma2(acc2[m][0], wa.y, v.y);
                    fma2(acc2[m][1], wb.x, v.x);
                    fma2(acc2[m][1], wb.y, v.y);
                }
            }
        }
    }

    if (MODE == 0) {
        // LayerNorm over the 128 outputs of each row, then ReLU
        __syncthreads();  // done reading s_in; reuse as row buffer
        float* s_f = reinterpret_cast<float*>(s_in);  // layout [node][132]
        #pragma unroll
        for (int m = 0; m < 16; m++) {
            float2 p = make_float2(sum2(acc2[m][0]), sum2(acc2[m][1]));
            *reinterpret_cast<float2*>(&s_f[(mbase + m) * 132 + j0]) = p;
        }
        __syncthreads();

        int wid = tid >> 5;
        #pragma unroll
        for (int q = 0; q < 8; q++) {
            int r = wid * 8 + q;
            float v0 = s_f[r * 132 + lane];
            float v1 = s_f[r * 132 + lane + 32];
            float v2 = s_f[r * 132 + lane + 64];
            float v3 = s_f[r * 132 + lane + 96];
            float s  = v0 + v1 + v2 + v3;
            float ss = v0 * v0 + v1 * v1 + v2 * v2 + v3 * v3;
            #pragma unroll
            for (int o = 16; o > 0; o >>= 1) {
                s  += __shfl_down_sync(0xFFFFFFFFu, s, o);
                ss += __shfl_down_sync(0xFFFFFFFFu, ss, o);
            }
            if (lane == 0) {
                float mu  = s * (1.0f / 128.0f);
                float var = ss * (1.0f / 128.0f) - mu * mu;
                s_mu[r] = mu;
                s_rs[r] = rsqrtf(var + 1e-5f);
            }
        }
        __syncthreads();

        float ga = __ldg(lng + j0), gb = __ldg(lng + j0 + 1);
        float ba = __ldg(lnb + j0), bb = __ldg(lnb + j0 + 1);
        #pragma unroll
        for (int m = 0; m < 16; m++) {
            int n = n0 + mbase + m;
            if (n < N_NODES) {
                int r = mbase + m;
                float2 p = *reinterpret_cast<float2*>(&s_f[r * 132 + j0]);
                float va = fmaxf((p.x - s_mu[r]) * s_rs[r] * ga + ba, 0.0f);
                float vb = fmaxf((p.y - s_mu[r]) * s_rs[r] * gb + bb, 0.0f);
                *reinterpret_cast<float2*>(&out[n * D + j0]) = make_float2(va, vb);
            }
        }
    } else {
        #pragma unroll
        for (int m = 0; m < 16; m++) {
            int n = n0 + mbase + m;
            if (n < N_NODES) {
                float va = sum2(acc2[m][0]);
                float vb = sum2(acc2[m][1]);
                if (MODE == 1) { va = fmaxf(va, 0.0f); vb = fmaxf(vb, 0.0f); }
                *reinterpret_cast<float2*>(&out[n * D + j0]) = make_float2(va, vb);
            }
        }
    }
}

// ---------------------------------------------------------------------------
// Launch: CSR build once, then 3 fused layer kernels
// ---------------------------------------------------------------------------
extern "C" void kernel_launch(void* const* d_in, const int* in_sizes, int n_in,
                              void* d_out, int out_size) {
    const float4* x   = (const float4*)d_in[0];
    const int*    ei  = (const int*)d_in[1];
    const int E       = in_sizes[1] / 2;
    const int* src = ei;
    const int* dst = ei + E;

    const float* Wl0 = (const float*)d_in[2];
    const float* bl0 = (const float*)d_in[3];
    const float* Wr0 = (const float*)d_in[4];
    const float* Wl1 = (const float*)d_in[5];
    const float* bl1 = (const float*)d_in[6];
    const float* Wr1 = (const float*)d_in[7];
    const float* Wl2 = (const float*)d_in[8];
    const float* bl2 = (const float*)d_in[9];
    const float* Wr2 = (const float*)d_in[10];
    const float* lng = (const float*)d_in[11];
    const float* lnb = (const float*)d_in[12];

    float4 *h1, *h2;
    cudaGetSymbolAddress((void**)&h1, g_h1);
    cudaGetSymbolAddress((void**)&h2, g_h2);

    float* out = (float*)d_out;

    const int edge_blocks = (E + 255) / 256;
    const int fused_blocks = (N_NODES + NPB - 1) / NPB;

    // ---- CSR build (once; reused by all 3 layers) ----
    zero_deg_kernel<<<(N_NODES + 255) / 256, 256>>>();
    hist_kernel<<<edge_blocks, 256>>>(dst, E);
    scan_kernel<<<1, 1024>>>();
    fill_kernel<<<edge_blocks, 256>>>(src, dst, E);

    // ---- layer 0: conv -> LN -> ReLU ----
    fused_kernel<0><<<fused_blocks, 128>>>(x, Wl0, bl0, Wr0, lng, lnb, (float*)h1);
    // ---- layer 1: conv -> ReLU ----
    fused_kernel<1><<<fused_blocks, 128>>>((const float4*)h1, Wl1, bl1, Wr1, lng, lnb, (float*)h2);
    // ---- layer 2: conv (no activation) ----
    fused_kernel<2><<<fused_blocks, 128>>>((const float4*)h2, Wl2, bl2, Wr2, lng, lnb, out);
}

// round 7
// speedup vs baseline: 1.2192x; 1.2192x over previous
#include <cuda_runtime.h>

#define N_NODES 50000
#define E_EDGES 800000
#define D 128
#define D4 32      // D in float4 units
#define NPB 32     // nodes per tile
#define NTILES ((N_NODES + NPB - 1) / NPB)
#define GTHREADS 512
#define GGRID 152
#define WSTRIDE 65 // float4 per j-pair row in weight smem (odd -> conflict-free)

// smem layout (dynamic): wl_s[64*65] | wr_s[64*65] | s_in[NPB*64] | mu[32] | rs[32]
#define SMEM_F4 (2 * 64 * WSTRIDE + NPB * 64)
#define SMEM_BYTES (SMEM_F4 * 16 + 64 * 4)

// Scratch (allocation-free rule: __device__ globals)
__device__ float4 g_agg[N_NODES * D4];
__device__ float4 g_h1[N_NODES * D4];
__device__ float4 g_h2[N_NODES * D4];
__device__ int    g_deg[N_NODES];
__device__ int    g_rowptr[N_NODES + 1];
__device__ int    g_cursor[N_NODES];
__device__ int    g_csrc[E_EDGES];

// ---------------------------------------------------------------------------
// packed f32x2 helpers
// ---------------------------------------------------------------------------
__device__ __forceinline__ void fma2(unsigned long long& d,
                                     unsigned long long a,
                                     unsigned long long b) {
    asm("fma.rn.f32x2 %0, %1, %2, %0;" : "+l"(d) : "l"(a), "l"(b));
}
__device__ __forceinline__ unsigned long long pack2(float lo, float hi) {
    unsigned long long r;
    asm("mov.b64 %0, {%1, %2};" : "=l"(r) : "f"(lo), "f"(hi));
    return r;
}
__device__ __forceinline__ float sum2(unsigned long long v) {
    float lo, hi;
    asm("mov.b64 {%0, %1}, %2;" : "=f"(lo), "=f"(hi) : "l"(v));
    return lo + hi;
}

// ---------------------------------------------------------------------------
// CSR build: zero degrees -> histogram -> scan -> fill src lists
// ---------------------------------------------------------------------------
__global__ void zero_deg_kernel() {
    int i = blockIdx.x * blockDim.x + threadIdx.x;
    if (i < N_NODES) g_deg[i] = 0;
}

__global__ void hist_kernel(const int* __restrict__ dst, int E) {
    int e = blockIdx.x * blockDim.x + threadIdx.x;
    if (e < E) atomicAdd(&g_deg[__ldg(dst + e)], 1);
}

__device__ __forceinline__ int warp_incl_scan(int v, int lane) {
    #pragma unroll
    for (int o = 1; o < 32; o <<= 1) {
        int t = __shfl_up_sync(0xFFFFFFFFu, v, o);
        if (lane >= o) v += t;
    }
    return v;
}

__global__ void __launch_bounds__(1024) scan_kernel() {
    __shared__ int s_warp[32];
    __shared__ int s_carry;
    int tid = threadIdx.x;
    int lane = tid & 31, wid = tid >> 5;
    if (tid == 0) s_carry = 0;
    __syncthreads();

    for (int base = 0; base < N_NODES; base += 1024) {
        int idx = base + tid;
        int v = (idx < N_NODES) ? g_deg[idx] : 0;
        int incl = warp_incl_scan(v, lane);
        if (lane == 31) s_warp[wid] = incl;
        __syncthreads();
        if (wid == 0) {
            int w = s_warp[lane];
            w = warp_incl_scan(w, lane);
            s_warp[lane] = w;
        }
        __syncthreads();
        int offset = (wid > 0) ? s_warp[wid - 1] : 0;
        int excl = s_carry + offset + incl - v;
        if (idx < N_NODES) {
            g_rowptr[idx] = excl;
            g_cursor[idx] = excl;
        }
        int chunk_total = s_warp[31];
        __syncthreads();
        if (tid == 0) s_carry += chunk_total;
        __syncthreads();
    }
    if (tid == 0) g_rowptr[N_NODES] = s_carry;
}

__global__ void fill_kernel(const int* __restrict__ src,
                            const int* __restrict__ dst, int E) {
    int e = blockIdx.x * blockDim.x + threadIdx.x;
    if (e >= E) return;
    int d = __ldg(dst + e);
    int pos = atomicAdd(&g_cursor[d], 1);
    g_csrc[pos] = __ldg(src + e);
}

// ---------------------------------------------------------------------------
// Aggregate: one warp per node, 16-deep MLP on the gather loads.
// ---------------------------------------------------------------------------
__global__ void __launch_bounds__(256)
aggregate_kernel(const float4* __restrict__ x, float4* __restrict__ agg) {
    int warp = (blockIdx.x * blockDim.x + threadIdx.x) >> 5;
    if (warp >= N_NODES) return;
    int lane = threadIdx.x & 31;
    int beg = __ldg(g_rowptr + warp);
    int end = __ldg(g_rowptr + warp + 1);

    float4 a = make_float4(0.f, 0.f, 0.f, 0.f);
    int i = beg;
    for (; i + 16 <= end; i += 16) {
        int s[16];
        #pragma unroll
        for (int u = 0; u < 16; u++) s[u] = __ldg(g_csrc + i + u);
        float4 v[16];
        #pragma unroll
        for (int u = 0; u < 16; u++) v[u] = __ldg(x + s[u] * D4 + lane);
        #pragma unroll
        for (int u = 0; u < 16; u++) {
            a.x += v[u].x; a.y += v[u].y; a.z += v[u].z; a.w += v[u].w;
        }
    }
    for (; i + 4 <= end; i += 4) {
        int s[4];
        #pragma unroll
        for (int u = 0; u < 4; u++) s[u] = __ldg(g_csrc + i + u);
        float4 v[4];
        #pragma unroll
        for (int u = 0; u < 4; u++) v[u] = __ldg(x + s[u] * D4 + lane);
        #pragma unroll
        for (int u = 0; u < 4; u++) {
            a.x += v[u].x; a.y += v[u].y; a.z += v[u].z; a.w += v[u].w;
        }
    }
    for (; i < end; i++) {
        int s = __ldg(g_csrc + i);
        float4 v = __ldg(x + s * D4 + lane);
        a.x += v.x; a.y += v.y; a.z += v.z; a.w += v.w;
    }
    agg[warp * D4 + lane] = a;
}

// ---------------------------------------------------------------------------
// Persistent GEMM: one block per SM, full Wl+Wr resident in smem (staged once,
// coalesced). Grid-strides over node tiles. 512 threads:
//   jh = tid & 63 (j pair -> j0 = 2*jh), mg = tid >> 6 (8 groups x 4 m rows)
// MODE 0: LayerNorm -> ReLU ; MODE 1: ReLU ; MODE 2: identity
// ---------------------------------------------------------------------------
template <int MODE>
__global__ void __launch_bounds__(GTHREADS)
gemm_persist(const float4* __restrict__ agg,
             const float4* __restrict__ hin,
             const float* __restrict__ Wl,
             const float* __restrict__ bl,
             const float* __restrict__ Wr,
             const float* __restrict__ lng,
             const float* __restrict__ lnb,
             float* __restrict__ out) {
    extern __shared__ float4 smem[];
    float4* wl_s = smem;                       // 64 * WSTRIDE
    float4* wr_s = smem + 64 * WSTRIDE;        // 64 * WSTRIDE
    float4* s_in = smem + 2 * 64 * WSTRIDE;    // NPB * 64
    float*  s_mu = reinterpret_cast<float*>(s_in + NPB * 64);
    float*  s_rs = s_mu + NPB;

    const int tid = threadIdx.x;
    const int jh = tid & 63;
    const int j0 = 2 * jh;
    const int mg = tid >> 6;       // 0..7
    const int mbase = mg * 4;
    const int lane = tid & 31;

    // ---- stage full weights once (coalesced: warp = one 128-float row) ----
    {
        const float4* Wl4 = reinterpret_cast<const float4*>(Wl);
        const float4* Wr4 = reinterpret_cast<const float4*>(Wr);
        #pragma unroll
        for (int idx = tid; idx < 128 * 32; idx += GTHREADS) {
            int j = idx >> 5, k4 = idx & 31;
            int soff = (j >> 1) * WSTRIDE + 2 * k4 + (j & 1);
            wl_s[soff] = __ldg(Wl4 + idx);
            wr_s[soff] = __ldg(Wr4 + idx);
        }
    }
    const unsigned long long bias_a = pack2(__ldg(bl + j0), 0.0f);
    const unsigned long long bias_b = pack2(__ldg(bl + j0 + 1), 0.0f);
    const float ga = __ldg(lng + j0), gb = __ldg(lng + j0 + 1);
    const float ba = __ldg(lnb + j0), bb = __ldg(lnb + j0 + 1);

    const ulonglong2* s_u = reinterpret_cast<const ulonglong2*>(s_in);

    for (int tile = blockIdx.x; tile < NTILES; tile += GGRID) {
        const int n0 = tile * NPB;
        __syncthreads();  // protect s_in reuse (weights stage / prev epilogue)

        // ---- stage tile inputs: agg rows (cols 0..31) + hin rows (32..63)
        #pragma unroll
        for (int i = tid; i < NPB * 64; i += GTHREADS) {
            int m = i >> 6, q = i & 63;
            int n = n0 + m;
            if (n >= N_NODES) n = N_NODES - 1;  // clamp
            s_in[i] = (q < 32) ? __ldg(agg + n * D4 + q)
                               : __ldg(hin + n * D4 + (q - 32));
        }
        __syncthreads();

        unsigned long long acc2[4][2];
        #pragma unroll
        for (int m = 0; m < 4; m++) { acc2[m][0] = bias_a; acc2[m][1] = bias_b; }

        // ---- mainloop: Wl x agg, then Wr x hin (all operands in smem)
        #pragma unroll 4
        for (int k4 = 0; k4 < 32; k4++) {
            ulonglong2 wa = *reinterpret_cast<const ulonglong2*>(&wl_s[jh * WSTRIDE + 2 * k4]);
            ulonglong2 wb = *reinterpret_cast<const ulonglong2*>(&wl_s[jh * WSTRIDE + 2 * k4 + 1]);
            #pragma unroll
            for (int m = 0; m < 4; m++) {
                ulonglong2 v = s_u[(mbase + m) * 64 + k4];
                fma2(acc2[m][0], wa.x, v.x);
                fma2(acc2[m][0], wa.y, v.y);
                fma2(acc2[m][1], wb.x, v.x);
                fma2(acc2[m][1], wb.y, v.y);
            }
        }
        #pragma unroll 4
        for (int k4 = 0; k4 < 32; k4++) {
            ulonglong2 wa = *reinterpret_cast<const ulonglong2*>(&wr_s[jh * WSTRIDE + 2 * k4]);
            ulonglong2 wb = *reinterpret_cast<const ulonglong2*>(&wr_s[jh * WSTRIDE + 2 * k4 + 1]);
            #pragma unroll
            for (int m = 0; m < 4; m++) {
                ulonglong2 v = s_u[(mbase + m) * 64 + 32 + k4];
                fma2(acc2[m][0], wa.x, v.x);
                fma2(acc2[m][0], wa.y, v.y);
                fma2(acc2[m][1], wb.x, v.x);
                fma2(acc2[m][1], wb.y, v.y);
            }
        }

        if (MODE == 0) {
            // LayerNorm over the 128 outputs of each row, then ReLU
            __syncthreads();  // done reading s_in; reuse as row buffer
            float* s_f = reinterpret_cast<float*>(s_in);  // [node][132]
            #pragma unroll
            for (int m = 0; m < 4; m++) {
                float2 p = make_float2(sum2(acc2[m][0]), sum2(acc2[m][1]));
                *reinterpret_cast<float2*>(&s_f[(mbase + m) * 132 + j0]) = p;
            }
            __syncthreads();

            int wid = tid >> 5;  // 0..15, each handles 2 rows
            #pragma unroll
            for (int q = 0; q < 2; q++) {
                int r = wid * 2 + q;
                float v0 = s_f[r * 132 + lane];
                float v1 = s_f[r * 132 + lane + 32];
                float v2 = s_f[r * 132 + lane + 64];
                float v3 = s_f[r * 132 + lane + 96];
                float s  = v0 + v1 + v2 + v3;
                float ss = v0 * v0 + v1 * v1 + v2 * v2 + v3 * v3;
                #pragma unroll
                for (int o = 16; o > 0; o >>= 1) {
                    s  += __shfl_down_sync(0xFFFFFFFFu, s, o);
                    ss += __shfl_down_sync(0xFFFFFFFFu, ss, o);
                }
                if (lane == 0) {
                    float mu  = s * (1.0f / 128.0f);
                    float var = ss * (1.0f / 128.0f) - mu * mu;
                    s_mu[r] = mu;
                    s_rs[r] = rsqrtf(var + 1e-5f);
                }
            }
            __syncthreads();

            #pragma unroll
            for (int m = 0; m < 4; m++) {
                int n = n0 + mbase + m;
                if (n < N_NODES) {
                    int r = mbase + m;
                    float2 p = *reinterpret_cast<float2*>(&s_f[r * 132 + j0]);
                    float va = fmaxf((p.x - s_mu[r]) * s_rs[r] * ga + ba, 0.0f);
                    float vb = fmaxf((p.y - s_mu[r]) * s_rs[r] * gb + bb, 0.0f);
                    *reinterpret_cast<float2*>(&out[n * D + j0]) = make_float2(va, vb);
                }
            }
        } else {
            #pragma unroll
            for (int m = 0; m < 4; m++) {
                int n = n0 + mbase + m;
                if (n < N_NODES) {
                    float va = sum2(acc2[m][0]);
                    float vb = sum2(acc2[m][1]);
                    if (MODE == 1) { va = fmaxf(va, 0.0f); vb = fmaxf(vb, 0.0f); }
                    *reinterpret_cast<float2*>(&out[n * D + j0]) = make_float2(va, vb);
                }
            }
        }
    }
}

// ---------------------------------------------------------------------------
// Launch: CSR build once, then 3 x (aggregate -> persistent gemm)
// ---------------------------------------------------------------------------
extern "C" void kernel_launch(void* const* d_in, const int* in_sizes, int n_in,
                              void* d_out, int out_size) {
    const float4* x   = (const float4*)d_in[0];
    const int*    ei  = (const int*)d_in[1];
    const int E       = in_sizes[1] / 2;
    const int* src = ei;
    const int* dst = ei + E;

    const float* Wl0 = (const float*)d_in[2];
    const float* bl0 = (const float*)d_in[3];
    const float* Wr0 = (const float*)d_in[4];
    const float* Wl1 = (const float*)d_in[5];
    const float* bl1 = (const float*)d_in[6];
    const float* Wr1 = (const float*)d_in[7];
    const float* Wl2 = (const float*)d_in[8];
    const float* bl2 = (const float*)d_in[9];
    const float* Wr2 = (const float*)d_in[10];
    const float* lng = (const float*)d_in[11];
    const float* lnb = (const float*)d_in[12];

    float4 *agg, *h1, *h2;
    cudaGetSymbolAddress((void**)&agg, g_agg);
    cudaGetSymbolAddress((void**)&h1, g_h1);
    cudaGetSymbolAddress((void**)&h2, g_h2);

    float* out = (float*)d_out;

    // allow >48KB dynamic smem (idempotent host-side attribute set)
    cudaFuncSetAttribute(gemm_persist<0>, cudaFuncAttributeMaxDynamicSharedMemorySize, SMEM_BYTES);
    cudaFuncSetAttribute(gemm_persist<1>, cudaFuncAttributeMaxDynamicSharedMemorySize, SMEM_BYTES);
    cudaFuncSetAttribute(gemm_persist<2>, cudaFuncAttributeMaxDynamicSharedMemorySize, SMEM_BYTES);

    const int edge_blocks = (E + 255) / 256;
    const int agg_blocks  = (N_NODES * 32 + 255) / 256;  // warp per node

    // ---- CSR build (once; reused by all 3 layers) ----
    zero_deg_kernel<<<(N_NODES + 255) / 256, 256>>>();
    hist_kernel<<<edge_blocks, 256>>>(dst, E);
    scan_kernel<<<1, 1024>>>();
    fill_kernel<<<edge_blocks, 256>>>(src, dst, E);

    // ---- layer 0: conv -> LN -> ReLU ----
    aggregate_kernel<<<agg_blocks, 256>>>(x, agg);
    gemm_persist<0><<<GGRID, GTHREADS, SMEM_BYTES>>>(agg, x, Wl0, bl0, Wr0, lng, lnb, (float*)h1);

    // ---- layer 1: conv -> ReLU ----
    aggregate_kernel<<<agg_blocks, 256>>>((const float4*)h1, agg);
    gemm_persist<1><<<GGRID, GTHREADS, SMEM_BYTES>>>(agg, (const float4*)h1, Wl1, bl1, Wr1, lng, lnb, (float*)h2);

    // ---- layer 2: conv (no activation) ----
    aggregate_kernel<<<agg_blocks, 256>>>((const float4*)h2, agg);
    gemm_persist<2><<<GGRID, GTHREADS, SMEM_BYTES>>>(agg, (const float4*)h2, Wl2, bl2, Wr2, lng, lnb, out);
}